// round 16
// baseline (speedup 1.0000x reference)
#include <cuda_runtime.h>
#include <cstdint>

#define OUT_F  4096
#define IN_F   4096
#define NFREQ  10000
#define ROWS   1024
#define SCALE  2.34375f      // 150 / sqrt(4096)

// ---- GEMM tile config (s8, 128x256, BK=64, 256 threads) ----
#define BM 128
#define BN 256
#define BK 64                        // s8 elems per stage = 64 B rows
#define KSTAGES (IN_F / BK)          // 64
#define SROW8 80                     // padded smem row bytes: 16B-aligned rows (ldmatrix/STS
                                     // require 16B alignment; 72 trapped), conflict-free
                                     // (bank step 20 -> 8 rows hit 8 distinct banks)
#define XBB (BM * SROW8)             // 10240 B
#define WBB (BN * SROW8)             // 20480 B
#define BUF8 (XBB + WBB)             // 30720 B
#define GEMM_SMEM (2 * BUF8)         // 61440 B

#define HSLOTS 16384
#define PREP_SMEM (HSLOTS * 8)       // skey + smax, 128 KB

// Scratch (static __device__ — no allocation allowed)
static __device__ float     g_y[(size_t)ROWS * OUT_F];       // 16 MB
static __device__ unsigned  g_x8[(size_t)ROWS * IN_F / 4];   // 4 MB   X int8
static __device__ unsigned  g_w8[(size_t)OUT_F * IN_F / 4];  // 16 MB  W int8
static __device__ float     g_dx[ROWS];                      // X row dequant scales
static __device__ float     g_dw[OUT_F];                     // W row dequant scales
static __device__ unsigned  g_pk[NFREQ];                     // (o<<16)|i
static __device__ float     g_sv[NFREQ];                     // valid ? spec : 0

// ======================== PTX helpers ======================================
static __device__ __forceinline__ uint32_t smem_u32(const void* p) {
    uint32_t a;
    asm("{ .reg .u64 t; cvta.to.shared.u64 t, %1; cvt.u32.u64 %0, t; }" : "=r"(a) : "l"(p));
    return a;
}

#define LDSM_X4(r, addr) \
    asm volatile("ldmatrix.sync.aligned.m8n8.x4.shared.b16 {%0,%1,%2,%3}, [%4];" \
                 : "=r"((r)[0]), "=r"((r)[1]), "=r"((r)[2]), "=r"((r)[3]) : "r"(addr))

#define MMA_S8(c, a, b0, b1) \
    asm volatile("mma.sync.aligned.m16n8k32.row.col.s32.s8.s8.s32 " \
                 "{%0,%1,%2,%3}, {%4,%5,%6,%7}, {%8,%9}, {%0,%1,%2,%3};" \
                 : "+r"((c)[0]), "+r"((c)[1]), "+r"((c)[2]), "+r"((c)[3]) \
                 : "r"((a)[0]), "r"((a)[1]), "r"((a)[2]), "r"((a)[3]), \
                   "r"(b0), "r"(b1))

static __device__ __forceinline__ unsigned pack4_s8(float a, float b, float c, float d, float qs) {
    int x0 = max(-127, min(127, __float2int_rn(a * qs)));
    int x1 = max(-127, min(127, __float2int_rn(b * qs)));
    int x2 = max(-127, min(127, __float2int_rn(c * qs)));
    int x3 = max(-127, min(127, __float2int_rn(d * qs)));
    return (unsigned)(x0 & 0xFF) | ((unsigned)(x1 & 0xFF) << 8) |
           ((unsigned)(x2 & 0xFF) << 16) | ((unsigned)(x3 & 0xFF) << 24);
}

// ============ setup: dedupe via smem open-addressing hash (1 CTA) ===========
__global__ __launch_bounds__(1024)
void k_prep(const void* __restrict__ idxv, const float* __restrict__ spec) {
    extern __shared__ unsigned hsm[];
    unsigned* skey = hsm;                 // HSLOTS
    int*      smax = (int*)(hsm + HSLOTS);
    __shared__ int s_is32;
    const int tid = threadIdx.x;

    for (int j = tid; j < HSLOTS; j += 1024) { skey[j] = 0xFFFFFFFFu; smax[j] = 0; }
    if (tid == 0) s_is32 = 0;
    __syncthreads();

    // dtype detect: reading NFREQ int64 = 80000 B = exact int32-layout buffer size
    const long long* p64 = (const long long*)idxv;
    for (int k = tid; k < NFREQ; k += 1024)
        if ((unsigned long long)p64[k] >= (unsigned long long)OUT_F) s_is32 = 1;
    __syncthreads();
    const bool is32 = (s_is32 != 0);

    unsigned pkl[(NFREQ + 1023) / 1024];
    int cnt = 0;
    for (int k = tid; k < NFREQ; k += 1024, ++cnt) {
        int o, i;
        if (is32) {
            const int* p = (const int*)idxv;
            o = p[k];           i = p[NFREQ + k];
        } else {
            o = (int)p64[k];    i = (int)p64[NFREQ + k];
        }
        o &= (OUT_F - 1);  i &= (IN_F - 1);
        unsigned pk = ((unsigned)o << 16) | (unsigned)i;
        pkl[cnt] = pk;
        unsigned h = (pk * 2654435761u) >> 18;      // 14-bit slot
        for (;;) {
            unsigned old = atomicCAS(&skey[h], 0xFFFFFFFFu, pk);
            if (old == 0xFFFFFFFFu || old == pk) { atomicMax(&smax[h], k + 1); break; }
            h = (h + 1) & (HSLOTS - 1);
        }
    }
    __syncthreads();

    cnt = 0;
    for (int k = tid; k < NFREQ; k += 1024, ++cnt) {
        unsigned pk = pkl[cnt];
        unsigned h = (pk * 2654435761u) >> 18;
        while (skey[h] != pk) h = (h + 1) & (HSLOTS - 1);
        bool valid = (smax[h] == k + 1);            // last update wins
        g_pk[k] = pk;
        g_sv[k] = valid ? spec[k] : 0.0f;
    }
}

// ====== fused pre-pass ======
// blocks [0,ROWS): per-row zero + scatter(smem atomics) + WHT + X->s8 quant
// blocks [ROWS, ROWS+2048): W->s8 quant, 2 rows/block with per-row absmax
__global__ __launch_bounds__(512)
void k_pre(const float* __restrict__ x, const float* __restrict__ w) {
    __shared__ __align__(16) float xrow[IN_F];
    __shared__ __align__(16) float yrow[OUT_F];
    __shared__ int s_am[2];
    const int tid = threadIdx.x;

    if (blockIdx.x >= ROWS) {
        // ---- W quant: rows 2b, 2b+1 ----
        const int b = blockIdx.x - ROWS;
        const int half = tid >> 8;           // 0 or 1
        const int t = tid & 255;
        const int row = 2 * b + half;
        const float4* wr = reinterpret_cast<const float4*>(w + (size_t)row * IN_F);
        float4 v[4];
        float am = 0.f;
        #pragma unroll
        for (int i = 0; i < 4; ++i) {
            v[i] = wr[t + i * 256];
            am = fmaxf(am, fmaxf(fmaxf(fabsf(v[i].x), fabsf(v[i].y)),
                                 fmaxf(fabsf(v[i].z), fabsf(v[i].w))));
        }
        if (tid < 2) s_am[tid] = 0;
        __syncthreads();
        atomicMax(&s_am[half], __float_as_int(am));
        __syncthreads();
        float amax = fmaxf(__int_as_float(s_am[half]), 1e-20f);
        float qs = 127.f / amax;
        if (t == 0) g_dw[row] = amax / 127.f;
        unsigned* dst = g_w8 + (size_t)row * (IN_F / 4);
        #pragma unroll
        for (int i = 0; i < 4; ++i)
            dst[t + i * 256] = pack4_s8(v[i].x, v[i].y, v[i].z, v[i].w, qs);
        return;
    }

    const int r = blockIdx.x;
    const float4* xg = reinterpret_cast<const float4*>(x + (size_t)r * IN_F);
    if (tid == 0) s_am[0] = 0;
    float am = 0.f;
    for (int j = tid; j < IN_F / 4; j += 512) {
        float4 v = xg[j];
        reinterpret_cast<float4*>(xrow)[j] = v;
        am = fmaxf(am, fmaxf(fmaxf(fabsf(v.x), fabsf(v.y)),
                             fmaxf(fabsf(v.z), fabsf(v.w))));
    }
    for (int j = tid; j < OUT_F / 4; j += 512)
        reinterpret_cast<float4*>(yrow)[j] = make_float4(0.f, 0.f, 0.f, 0.f);
    atomicMax(&s_am[0], __float_as_int(am));
    __syncthreads();

    {   // X -> s8 (row already in smem)
        float amax = fmaxf(__int_as_float(s_am[0]), 1e-20f);
        float qs = 127.f / amax;
        if (tid == 0) g_dx[r] = amax / 127.f;
        unsigned* dst = g_x8 + (size_t)r * (IN_F / 4);
        for (int j = tid; j < IN_F / 4; j += 512)
            dst[j] = pack4_s8(xrow[4 * j], xrow[4 * j + 1], xrow[4 * j + 2], xrow[4 * j + 3], qs);
    }

    for (int k = tid; k < NFREQ; k += 512) {
        unsigned pk = g_pk[k];
        float s = g_sv[k];
        atomicAdd(&yrow[pk >> 16], xrow[pk & 0xFFFF] * s);
    }
    __syncthreads();

    for (int len = 1; len < OUT_F; len <<= 1) {
        for (int p = tid; p < OUT_F / 2; p += 512) {
            int i0 = 2 * p - (p & (len - 1));
            int i1 = i0 + len;
            float a = yrow[i0], b = yrow[i1];
            yrow[i0] = a + b;
            yrow[i1] = a - b;
        }
        __syncthreads();
    }

    float* yo = g_y + (size_t)r * OUT_F;
    for (int j = tid; j < OUT_F; j += 512) yo[j] = yrow[j] * SCALE;
}

// ======================== s8 mma.sync GEMM (128x256) ========================
// out[r,o] = dx[r]*dw[o]*(Xq · Wq^T)[r,o] + g_y[r,o]
// 8 warps (2M x 4N), warp tile 64x64, m16n8k32.s8, BK=64, double buffer.
__global__ __launch_bounds__(256, 1)
void k_gemm_s8(float* __restrict__ out) {
    extern __shared__ __align__(16) char smem[];
    const uint32_t sb = smem_u32(smem);

    const int tid  = threadIdx.x;
    const int wid  = tid >> 5;
    const int lane = tid & 31;
    const int warpM = wid >> 2;          // 0..1 (64 rows)
    const int warpN = wid & 3;           // 0..3 (64 cols)
    const int bn = blockIdx.x;           // 0..15
    const int bm = blockIdx.y;           // 0..7

    const char* xg = (const char*)g_x8 + (size_t)bm * BM * IN_F;
    const char* wg = (const char*)g_w8 + (size_t)bn * BN * IN_F;

    // Loaders: X = 512 x 16B (2/thread), W = 1024 x 16B (4/thread)
    int xr[2], xc[2], xsb[2];
    #pragma unroll
    for (int t = 0; t < 2; ++t) {
        int f = tid + t * 256;
        xr[t] = f >> 2;  xc[t] = (f & 3) * 16;
        xsb[t] = xr[t] * SROW8 + xc[t];
    }
    int wr[4], wc[4], wsb[4];
    #pragma unroll
    for (int t = 0; t < 4; ++t) {
        int f = tid + t * 256;
        wr[t] = f >> 2;  wc[t] = (f & 3) * 16;
        wsb[t] = wr[t] * SROW8 + wc[t];
    }

    // ldmatrix per-lane byte offsets
    uint32_t aoff[4];
    #pragma unroll
    for (int mt = 0; mt < 4; ++mt) {
        int rr = warpM * 64 + mt * 16 + (lane & 15);
        aoff[mt] = (uint32_t)(rr * SROW8 + (lane >> 4) * 16);
    }
    uint32_t boff[4];
    #pragma unroll
    for (int p = 0; p < 4; ++p) {
        int rr = warpN * 64 + p * 16 + (lane & 7) + ((lane >> 4) & 1) * 8;
        boff[p] = (uint32_t)(rr * SROW8 + ((lane >> 3) & 1) * 16);
    }

    int acc[4][8][4];
    #pragma unroll
    for (int mt = 0; mt < 4; ++mt)
        #pragma unroll
        for (int nt = 0; nt < 8; ++nt)
            #pragma unroll
            for (int j = 0; j < 4; ++j) acc[mt][nt][j] = 0;

    // Prologue: stage 0 -> buffer 0
    #pragma unroll
    for (int t = 0; t < 2; ++t)
        *reinterpret_cast<uint4*>(smem + xsb[t]) =
            *reinterpret_cast<const uint4*>(xg + (size_t)xr[t] * IN_F + xc[t]);
    #pragma unroll
    for (int t = 0; t < 4; ++t)
        *reinterpret_cast<uint4*>(smem + XBB + wsb[t]) =
            *reinterpret_cast<const uint4*>(wg + (size_t)wr[t] * IN_F + wc[t]);
    __syncthreads();

    for (int s = 0; s < KSTAGES; ++s) {
        const int buf = s & 1;
        const uint32_t xsu = sb + buf * BUF8;
        const uint32_t wsu = xsu + XBB;

        uint4 px[2], pw[4];
        const bool more = (s + 1) < KSTAGES;
        if (more) {
            const int kk = (s + 1) * BK;
            #pragma unroll
            for (int t = 0; t < 2; ++t)
                px[t] = *reinterpret_cast<const uint4*>(xg + (size_t)xr[t] * IN_F + kk + xc[t]);
            #pragma unroll
            for (int t = 0; t < 4; ++t)
                pw[t] = *reinterpret_cast<const uint4*>(wg + (size_t)wr[t] * IN_F + kk + wc[t]);
        }

        #pragma unroll
        for (int ks = 0; ks < 2; ++ks) {         // 2 x K=32 per stage
            uint32_t a[4][4], bq[4][4];
            #pragma unroll
            for (int mt = 0; mt < 4; ++mt) LDSM_X4(a[mt], xsu + aoff[mt] + ks * 32);
            #pragma unroll
            for (int p = 0; p < 4; ++p)  LDSM_X4(bq[p], wsu + boff[p] + ks * 32);
            #pragma unroll
            for (int mt = 0; mt < 4; ++mt)
                #pragma unroll
                for (int p = 0; p < 4; ++p) {
                    MMA_S8(acc[mt][2 * p],     a[mt], bq[p][0], bq[p][1]);
                    MMA_S8(acc[mt][2 * p + 1], a[mt], bq[p][2], bq[p][3]);
                }
        }

        if (more) {
            char* xb = smem + (buf ^ 1) * BUF8;
            #pragma unroll
            for (int t = 0; t < 2; ++t)
                *reinterpret_cast<uint4*>(xb + xsb[t]) = px[t];
            #pragma unroll
            for (int t = 0; t < 4; ++t)
                *reinterpret_cast<uint4*>(xb + XBB + wsb[t]) = pw[t];
        }
        __syncthreads();
    }

    // Epilogue: dequant + fuse +g_y.
    // c0,c1 at (row, 2*tid4), c2,c3 at (row+8, 2*tid4).
    const int gid  = lane >> 2;
    const int tid4 = lane & 3;
    #pragma unroll
    for (int mt = 0; mt < 4; ++mt) {
        const int r0 = bm * BM + warpM * 64 + mt * 16 + gid;
        const float dxa = g_dx[r0];
        const float dxb = g_dx[r0 + 8];
        #pragma unroll
        for (int nt = 0; nt < 8; ++nt) {
            const int c = bn * BN + warpN * 64 + nt * 8 + tid4 * 2;
            float2 dwv = *reinterpret_cast<const float2*>(&g_dw[c]);
            size_t i0 = (size_t)r0 * OUT_F + c;
            size_t i1 = (size_t)(r0 + 8) * OUT_F + c;
            float2 y0 = *reinterpret_cast<const float2*>(&g_y[i0]);
            float2 y1 = *reinterpret_cast<const float2*>(&g_y[i1]);
            float2 o0 = make_float2(fmaf((float)acc[mt][nt][0], dxa * dwv.x, y0.x),
                                    fmaf((float)acc[mt][nt][1], dxa * dwv.y, y0.y));
            float2 o1 = make_float2(fmaf((float)acc[mt][nt][2], dxb * dwv.x, y1.x),
                                    fmaf((float)acc[mt][nt][3], dxb * dwv.y, y1.y));
            *reinterpret_cast<float2*>(&out[i0]) = o0;
            *reinterpret_cast<float2*>(&out[i1]) = o1;
        }
    }
}

// ---------------------------------------------------------------------------
extern "C" void kernel_launch(void* const* d_in, const int* in_sizes, int n_in,
                              void* d_out, int out_size) {
    const float* x    = (const float*)d_in[0];   // [2,512,4096]
    const float* w    = (const float*)d_in[1];   // [4096,4096]
    const float* spec = (const float*)d_in[2];   // [10000]
    const void*  idx  = d_in[3];                 // [2,10000] int32 or int64
    float* out = (float*)d_out;                  // [2,512,4096]
    (void)in_sizes; (void)n_in; (void)out_size;

    cudaFuncSetAttribute(k_prep,    cudaFuncAttributeMaxDynamicSharedMemorySize, PREP_SMEM);
    cudaFuncSetAttribute(k_gemm_s8, cudaFuncAttributeMaxDynamicSharedMemorySize, GEMM_SMEM);

    k_prep   <<<1, 1024, PREP_SMEM>>>(idx, spec);
    k_pre    <<<ROWS + OUT_F / 2, 512>>>(x, w);
    k_gemm_s8<<<dim3(OUT_F / BN, ROWS / BM), 256, GEMM_SMEM>>>(out);
}

// round 17
// speedup vs baseline: 1.9501x; 1.9501x over previous
#include <cuda_runtime.h>
#include <cuda_bf16.h>
#include <cstdint>

#define OUT_F  4096
#define IN_F   4096
#define NFREQ  10000
#define ROWS   1024
#define SCALE  2.34375f      // 150 / sqrt(4096)

// ---- GEMM tile config (bf16, 128x256, 256 thr, 8 warps x 64x64) ----
#define BM 128
#define BN 256
#define BK 32                        // bf16 elems per stage
#define KSTAGES (IN_F / BK)          // 128
#define SROWB 40                     // padded smem row in bf16 (80 B): 16B-aligned, conflict-free
#define XB_BYTES (BM * SROWB * 2)    // 10240 B
#define WB_BYTES (BN * SROWB * 2)    // 20480 B
#define BUFB (XB_BYTES + WB_BYTES)   // 30720 B per stage
#define GEMM_SMEM (2 * BUFB)         // 61440 B

// Scratch (static __device__ — no allocation allowed)
static __device__ float          g_y[(size_t)ROWS * OUT_F];     // 16 MB
static __device__ int            g_last[(size_t)OUT_F * IN_F];  // 64 MB hash (10k slots touched)
static __device__ __nv_bfloat16  g_wb[(size_t)OUT_F * IN_F];    // 32 MB  W bf16
static __device__ __nv_bfloat16  g_xb[(size_t)ROWS * IN_F];     // 8 MB   X bf16
static __device__ unsigned       g_key[NFREQ];
static __device__ unsigned       g_pk[NFREQ];                   // (o<<16)|i
static __device__ float          g_sv[NFREQ];                   // valid ? spec : 0
static __device__ int            g_is32;

// ======================== PTX helpers ======================================
static __device__ __forceinline__ uint32_t smem_u32(const void* p) {
    uint32_t a;
    asm("{ .reg .u64 t; cvta.to.shared.u64 t, %1; cvt.u32.u64 %0, t; }" : "=r"(a) : "l"(p));
    return a;
}

#define LDSM_X4(r, addr) \
    asm volatile("ldmatrix.sync.aligned.m8n8.x4.shared.b16 {%0,%1,%2,%3}, [%4];" \
                 : "=r"((r)[0]), "=r"((r)[1]), "=r"((r)[2]), "=r"((r)[3]) : "r"(addr))

#define LDSM_X2(r, addr) \
    asm volatile("ldmatrix.sync.aligned.m8n8.x2.shared.b16 {%0,%1}, [%2];" \
                 : "=r"((r)[0]), "=r"((r)[1]) : "r"(addr))

#define MMA_BF16(c, a, b) \
    asm volatile("mma.sync.aligned.m16n8k16.row.col.f32.bf16.bf16.f32 " \
                 "{%0,%1,%2,%3}, {%4,%5,%6,%7}, {%8,%9}, {%0,%1,%2,%3};" \
                 : "+f"((c)[0]), "+f"((c)[1]), "+f"((c)[2]), "+f"((c)[3]) \
                 : "r"((a)[0]), "r"((a)[1]), "r"((a)[2]), "r"((a)[3]), \
                   "r"((b)[0]), "r"((b)[1]))

// ================= prep: multi-CTA 4-kernel dedupe chain ====================
__global__ void k_detect(const long long* __restrict__ idx) {
    int k = blockIdx.x * blockDim.x + threadIdx.x;
    if (k == 0) g_is32 = 0;              // benign race with atomicOr below? no:
    // ensure reset happens via separate path: use two-phase within kernel is
    // unsafe; instead reset done by ALL threads writing 0 is wrong. Use trick:
    // g_is32 is only ever set by atomicOr(1); reset must precede. We reset in
    // block 0 thread 0 AND rely on... NOT safe across blocks. So: detect uses
    // atomicOr on a value that k_key reads; reset handled by k_detect writing
    // compare-base: we instead recompute cleanly:
    if (k < NFREQ) {
        unsigned long long v = (unsigned long long)idx[k];
        if (v >= (unsigned long long)OUT_F) atomicOr(&g_is32, 2);  // set bit1
    }
    // bit0 never set; see k_key: is32 = (g_is32 & 2). Reset below.
}

// decode (o,i) per entry under detected dtype; pack keys; clear hash slots;
// ALSO reset g_is32 for next replay (safe: everyone reads it first).
__global__ void k_key(const void* __restrict__ idxv) {
    int k = blockIdx.x * blockDim.x + threadIdx.x;
    if (k >= NFREQ) return;
    const bool is32 = (g_is32 & 2) != 0;
    int o, i;
    if (is32) {
        const int* p = (const int*)idxv;
        o = p[k];           i = p[NFREQ + k];
    } else {
        const long long* p = (const long long*)idxv;
        o = (int)p[k];      i = (int)p[NFREQ + k];
    }
    o &= (OUT_F - 1);  i &= (IN_F - 1);
    unsigned key = (unsigned)o * (unsigned)IN_F + (unsigned)i;
    g_key[k] = key;
    g_pk[k]  = ((unsigned)o << 16) | (unsigned)i;
    g_last[key] = 0;
    if (k == 0) g_is32 = 0;   // reset for next graph replay (read above first)
}

__global__ void k_hfill() {
    int k = blockIdx.x * blockDim.x + threadIdx.x;
    if (k < NFREQ) atomicMax(&g_last[g_key[k]], k + 1);
}

__global__ void k_hvalid(const float* __restrict__ spec) {
    int k = blockIdx.x * blockDim.x + threadIdx.x;
    if (k >= NFREQ) return;
    bool valid = (g_last[g_key[k]] == k + 1);   // last update wins
    g_sv[k] = valid ? spec[k] : 0.0f;
}

// ===== fused pre-pass: blocks [0,ROWS) = scatter+WHT+X->bf16; rest = W->bf16 =====
__global__ __launch_bounds__(512)
void k_pre(const float* __restrict__ x, const float* __restrict__ w) {
    __shared__ __align__(16) float xrow[IN_F];
    __shared__ __align__(16) float yrow[OUT_F];
    const int tid = threadIdx.x;

    if (blockIdx.x >= ROWS) {
        // ---- W -> bf16 slice: 2048 float4 per block ----
        size_t base = (size_t)(blockIdx.x - ROWS) * 2048;
        __nv_bfloat162* d = reinterpret_cast<__nv_bfloat162*>(g_wb);
        #pragma unroll
        for (int t = 0; t < 4; ++t) {
            size_t q = base + t * 512 + tid;
            float4 v = reinterpret_cast<const float4*>(w)[q];
            d[2 * q]     = __floats2bfloat162_rn(v.x, v.y);
            d[2 * q + 1] = __floats2bfloat162_rn(v.z, v.w);
        }
        return;
    }

    const int r = blockIdx.x;
    const float4* xg = reinterpret_cast<const float4*>(x + (size_t)r * IN_F);
    for (int j = tid; j < IN_F / 4; j += 512)
        reinterpret_cast<float4*>(xrow)[j] = xg[j];
    for (int j = tid; j < OUT_F / 4; j += 512)
        reinterpret_cast<float4*>(yrow)[j] = make_float4(0.f, 0.f, 0.f, 0.f);
    __syncthreads();

    {   // X -> bf16 (row already in smem)
        __nv_bfloat162* xb = reinterpret_cast<__nv_bfloat162*>(g_xb + (size_t)r * IN_F);
        for (int j = tid; j < IN_F / 2; j += 512)
            xb[j] = __floats2bfloat162_rn(xrow[2 * j], xrow[2 * j + 1]);
    }

    for (int k = tid; k < NFREQ; k += 512) {
        unsigned pk = g_pk[k];
        float s = g_sv[k];
        atomicAdd(&yrow[pk >> 16], xrow[pk & 0xFFFF] * s);
    }
    __syncthreads();

    for (int len = 1; len < OUT_F; len <<= 1) {
        for (int p = tid; p < OUT_F / 2; p += 512) {
            int i0 = 2 * p - (p & (len - 1));
            int i1 = i0 + len;
            float a = yrow[i0], b = yrow[i1];
            yrow[i0] = a + b;
            yrow[i1] = a - b;
        }
        __syncthreads();
    }

    float* yo = g_y + (size_t)r * OUT_F;
    for (int j = tid; j < OUT_F; j += 512) yo[j] = yrow[j] * SCALE;
}

// ======================== bf16 mma.sync GEMM (R13, known-good) ==============
// out[r,o] = (X · W^T)[r,o] + g_y[r,o]
// 8 warps (2M x 4N), warp tile 64x64, m16n8k16, double buffer, single wave.
__global__ __launch_bounds__(256, 1)
void k_gemm_bf16(float* __restrict__ out) {
    extern __shared__ __align__(16) char smem[];
    const uint32_t sb = smem_u32(smem);

    const int tid  = threadIdx.x;
    const int wid  = tid >> 5;
    const int lane = tid & 31;
    const int warpM = wid >> 2;          // 0..1
    const int warpN = wid & 3;           // 0..3 (64 cols each)
    const int bn = blockIdx.x;           // 0..15
    const int bm = blockIdx.y;           // 0..7

    const __nv_bfloat16* xg = g_xb + (size_t)bm * BM * IN_F;
    const __nv_bfloat16* wg = g_wb + (size_t)bn * BN * IN_F;

    // Loaders: X = 512 uint4 (2/thread), W = 1024 uint4 (4/thread).
    int xrow_[2], xcol_[2], xsb_[2];
    #pragma unroll
    for (int t = 0; t < 2; ++t) {
        int f = tid + t * 256;
        xrow_[t] = f >> 2;
        xcol_[t] = (f & 3) * 8;
        xsb_[t]  = (f >> 2) * (SROWB * 2) + (f & 3) * 16;
    }
    int wrow_[4], wcol_[4], wsb_[4];
    #pragma unroll
    for (int t = 0; t < 4; ++t) {
        int f = tid + t * 256;
        wrow_[t] = f >> 2;
        wcol_[t] = (f & 3) * 8;
        wsb_[t]  = (f >> 2) * (SROWB * 2) + (f & 3) * 16;
    }

    uint32_t aoff[4];
    #pragma unroll
    for (int mt = 0; mt < 4; ++mt) {
        int rr = warpM * 64 + mt * 16 + (lane & 15);
        aoff[mt] = (uint32_t)(rr * (SROWB * 2) + (lane >> 4) * 16);
    }
    uint32_t boff[8];
    #pragma unroll
    for (int nt = 0; nt < 8; ++nt) {
        int rr = warpN * 64 + nt * 8 + (lane & 7);
        boff[nt] = (uint32_t)(rr * (SROWB * 2) + ((lane >> 3) & 1) * 16);
    }

    float acc[4][8][4];
    #pragma unroll
    for (int mt = 0; mt < 4; ++mt)
        #pragma unroll
        for (int nt = 0; nt < 8; ++nt)
            #pragma unroll
            for (int j = 0; j < 4; ++j) acc[mt][nt][j] = 0.f;

    // Prologue: stage 0 -> buffer 0
    #pragma unroll
    for (int t = 0; t < 2; ++t)
        *reinterpret_cast<uint4*>(smem + xsb_[t]) =
            *reinterpret_cast<const uint4*>(xg + (size_t)xrow_[t] * IN_F + xcol_[t]);
    #pragma unroll
    for (int t = 0; t < 4; ++t)
        *reinterpret_cast<uint4*>(smem + XB_BYTES + wsb_[t]) =
            *reinterpret_cast<const uint4*>(wg + (size_t)wrow_[t] * IN_F + wcol_[t]);
    __syncthreads();

    for (int s = 0; s < KSTAGES; ++s) {
        const int buf = s & 1;
        const uint32_t xsu = sb + buf * BUFB;
        const uint32_t wsu = xsu + XB_BYTES;

        uint4 px[2], pw[4];
        const bool more = (s + 1) < KSTAGES;
        if (more) {
            const int kk = (s + 1) * BK;
            #pragma unroll
            for (int t = 0; t < 2; ++t)
                px[t] = *reinterpret_cast<const uint4*>(xg + (size_t)xrow_[t] * IN_F + kk + xcol_[t]);
            #pragma unroll
            for (int t = 0; t < 4; ++t)
                pw[t] = *reinterpret_cast<const uint4*>(wg + (size_t)wrow_[t] * IN_F + kk + wcol_[t]);
        }

        #pragma unroll
        for (int ks = 0; ks < 2; ++ks) {           // 2 x K=16 per stage
            uint32_t a[4][4], b[8][2];
            #pragma unroll
            for (int mt = 0; mt < 4; ++mt) LDSM_X4(a[mt], xsu + aoff[mt] + ks * 32);
            #pragma unroll
            for (int nt = 0; nt < 8; ++nt) LDSM_X2(b[nt], wsu + boff[nt] + ks * 32);
            #pragma unroll
            for (int mt = 0; mt < 4; ++mt)
                #pragma unroll
                for (int nt = 0; nt < 8; ++nt)
                    MMA_BF16(acc[mt][nt], a[mt], b[nt]);
        }

        if (more) {
            char* xb = smem + (buf ^ 1) * BUFB;
            #pragma unroll
            for (int t = 0; t < 2; ++t)
                *reinterpret_cast<uint4*>(xb + xsb_[t]) = px[t];
            #pragma unroll
            for (int t = 0; t < 4; ++t)
                *reinterpret_cast<uint4*>(xb + XB_BYTES + wsb_[t]) = pw[t];
        }
        __syncthreads();
    }

    // Epilogue: c0,c1 at (row, 2*tid4), c2,c3 at (row+8); fuse +g_y.
    const int gid  = lane >> 2;
    const int tid4 = lane & 3;
    #pragma unroll
    for (int mt = 0; mt < 4; ++mt) {
        const int r0 = bm * BM + warpM * 64 + mt * 16 + gid;
        #pragma unroll
        for (int nt = 0; nt < 8; ++nt) {
            const int c = bn * BN + warpN * 64 + nt * 8 + tid4 * 2;
            size_t i0 = (size_t)r0 * OUT_F + c;
            size_t i1 = (size_t)(r0 + 8) * OUT_F + c;
            float2 y0 = *reinterpret_cast<const float2*>(&g_y[i0]);
            float2 y1 = *reinterpret_cast<const float2*>(&g_y[i1]);
            float2 o0 = make_float2(acc[mt][nt][0] + y0.x, acc[mt][nt][1] + y0.y);
            float2 o1 = make_float2(acc[mt][nt][2] + y1.x, acc[mt][nt][3] + y1.y);
            *reinterpret_cast<float2*>(&out[i0]) = o0;
            *reinterpret_cast<float2*>(&out[i1]) = o1;
        }
    }
}

// ---------------------------------------------------------------------------
extern "C" void kernel_launch(void* const* d_in, const int* in_sizes, int n_in,
                              void* d_out, int out_size) {
    const float* x    = (const float*)d_in[0];   // [2,512,4096]
    const float* w    = (const float*)d_in[1];   // [4096,4096]
    const float* spec = (const float*)d_in[2];   // [10000]
    const void*  idx  = d_in[3];                 // [2,10000] int32 or int64
    float* out = (float*)d_out;                  // [2,512,4096]
    (void)in_sizes; (void)n_in; (void)out_size;

    cudaFuncSetAttribute(k_gemm_bf16, cudaFuncAttributeMaxDynamicSharedMemorySize, GEMM_SMEM);

    const int NB = (NFREQ + 255) / 256;
    k_detect   <<<NB, 256>>>((const long long*)idx);
    k_key      <<<NB, 256>>>(idx);
    k_hfill    <<<NB, 256>>>();
    k_hvalid   <<<NB, 256>>>(spec);
    k_pre      <<<ROWS + 2048, 512>>>(x, w);
    k_gemm_bf16<<<dim3(OUT_F / BN, ROWS / BM), 256, GEMM_SMEM>>>(out);
}